// round 13
// baseline (speedup 1.0000x reference)
#include <cuda_runtime.h>
#include <cuda_bf16.h>
#include <cuda_fp16.h>
#include <cstdint>

// Problem: MaskedSelfAttention  B=2, S=2048, E=1024, H=16, D=64, causal.
// R13: 3-stage cp.async pipelines (wait_group 1) in both GEMMs and attention.
//      Arithmetic unchanged -> rel_err canary 6.582877e-4.

#define TS   2048
#define EMB  1024
#define NHEADS 16
#define HD   64
#define ROWS (2*TS)

__device__ __half g_Qh[ROWS*EMB];
__device__ __half g_Kh[ROWS*EMB];
__device__ __half g_Vh[ROWS*EMB];
__device__ __half g_Ah[ROWS*EMB];
__device__ __half g_Xh[ROWS*EMB];
__device__ __half g_Wqh[EMB*EMB];
__device__ __half g_Wkh[EMB*EMB];
__device__ __half g_Wvh[EMB*EMB];
__device__ __half g_Woh[EMB*EMB];

__device__ __forceinline__ void mma_f16(float* d, const uint32_t* a, const uint32_t* b) {
    asm volatile(
        "mma.sync.aligned.m16n8k16.row.col.f32.f16.f16.f32 "
        "{%0,%1,%2,%3}, {%4,%5,%6,%7}, {%8,%9}, {%0,%1,%2,%3};"
        : "+f"(d[0]), "+f"(d[1]), "+f"(d[2]), "+f"(d[3])
        : "r"(a[0]), "r"(a[1]), "r"(a[2]), "r"(a[3]), "r"(b[0]), "r"(b[1]));
}

__device__ __forceinline__ uint32_t pack_h2(float x, float y) {
    __half2 h = __floats2half2_rn(x, y);
    return *(uint32_t*)&h;
}

__device__ __forceinline__ void ldm_x4(uint32_t& r0, uint32_t& r1,
                                       uint32_t& r2, uint32_t& r3, uint32_t addr) {
    asm volatile("ldmatrix.sync.aligned.m8n8.x4.shared.b16 {%0,%1,%2,%3}, [%4];"
        : "=r"(r0), "=r"(r1), "=r"(r2), "=r"(r3) : "r"(addr));
}
__device__ __forceinline__ void ldm_x4_t(uint32_t& r0, uint32_t& r1,
                                         uint32_t& r2, uint32_t& r3, uint32_t addr) {
    asm volatile("ldmatrix.sync.aligned.m8n8.x4.trans.shared.b16 {%0,%1,%2,%3}, [%4];"
        : "=r"(r0), "=r"(r1), "=r"(r2), "=r"(r3) : "r"(addr));
}

__device__ __forceinline__ void cp16(uint32_t saddr, const void* g) {
    asm volatile("cp.async.cg.shared.global [%0], [%1], 16;" :: "r"(saddr), "l"(g));
}
#define CP_COMMIT() asm volatile("cp.async.commit_group;" ::: "memory")
#define CP_WAIT0()  asm volatile("cp.async.wait_group 0;" ::: "memory")
#define CP_WAIT1()  asm volatile("cp.async.wait_group 1;" ::: "memory")

// exp2 on the FMA/ALU pipes (no MUFU).
__device__ __forceinline__ float exp2p(float d) {
    d = fmaxf(d, -120.f);
    float t = d + 12582912.f;
    float f = d - (t - 12582912.f);
    uint32_t e = (__float_as_uint(t) + (127u - 0x4B400000u)) << 23;
    float p = 1.3333558146e-3f;
    p = fmaf(p, f, 9.6181291076e-3f);
    p = fmaf(p, f, 5.5504108665e-2f);
    p = fmaf(p, f, 2.4022650696e-1f);
    p = fmaf(p, f, 6.9314718056e-1f);
    p = fmaf(p, f, 1.0f);
    return p * __uint_as_float(e);
}

__device__ __forceinline__ float qmax(float v) {
    v = fmaxf(v, __shfl_xor_sync(0xffffffffu, v, 1));
    v = fmaxf(v, __shfl_xor_sync(0xffffffffu, v, 2));
    return v;
}
__device__ __forceinline__ float qsum(float v) {
    v += __shfl_xor_sync(0xffffffffu, v, 1);
    v += __shfl_xor_sync(0xffffffffu, v, 2);
    return v;
}

// ---------------------------------------------------------------------------
// Prepass: convert x (4M) + 4 weights (1M each) fp32 -> fp16. 8 elems/thread.
// ---------------------------------------------------------------------------
__global__ __launch_bounds__(256) void cvt_all(
    const float* __restrict__ X,
    const float* __restrict__ Wq, const float* __restrict__ Wk,
    const float* __restrict__ Wv, const float* __restrict__ Wo,
    __half* __restrict__ Xh, __half* __restrict__ Wqh, __half* __restrict__ Wkh,
    __half* __restrict__ Wvh, __half* __restrict__ Woh)
{
    size_t i = ((size_t)blockIdx.x * 256 + threadIdx.x) * 8;
    const float* src; __half* dst; size_t off;
    const size_t NX = (size_t)ROWS * EMB, NW = (size_t)EMB * EMB;
    if (i < NX)               { src = X;  dst = Xh;  off = i; }
    else if (i < NX + NW)     { src = Wq; dst = Wqh; off = i - NX; }
    else if (i < NX + 2*NW)   { src = Wk; dst = Wkh; off = i - NX - NW; }
    else if (i < NX + 3*NW)   { src = Wv; dst = Wvh; off = i - NX - 2*NW; }
    else                      { src = Wo; dst = Woh; off = i - NX - 3*NW; }
    float4 a = *(const float4*)&src[off];
    float4 b = *(const float4*)&src[off + 4];
    uint4 u = make_uint4(pack_h2(a.x, a.y), pack_h2(a.z, a.w),
                         pack_h2(b.x, b.y), pack_h2(b.z, b.w));
    *(uint4*)&dst[off] = u;
}

// ---------------------------------------------------------------------------
// fp16 GEMM: CTA 128x128, BK=64, 8 warps, cp.async 3-stage pipeline.
// Row stride KW=36 words -> frag address 4g+tig conflict-free.
// ---------------------------------------------------------------------------
#define KW 36
#define TILE_W (128 * KW)
#define BUF_W  (2 * TILE_W)                 // A + B per stage (words)
#define GEMM_SMEM (3 * BUF_W * 4)           // 110592 B

template <bool OUTHALF>
__device__ __forceinline__ void gemm_h_body(
    const __half* __restrict__ A, const __half* __restrict__ B,
    const float* __restrict__ bias, void* __restrict__ Cptr,
    int bm, int bn, uint32_t* sm)
{
    const uint32_t smb = (uint32_t)__cvta_generic_to_shared(sm);
    const int tid  = threadIdx.x;
    const int lane = tid & 31, warp = tid >> 5;
    const int g    = lane >> 2, tig = lane & 3;
    const int wm   = warp >> 1, wn = warp & 1;

    int lrow[4], lc[4];
#pragma unroll
    for (int it = 0; it < 4; it++) {
        int v = tid + it * 256;
        lrow[it] = v >> 3;
        lc[it]   = (v & 7) * 8;
    }

    float acc[2][8][4];
#pragma unroll
    for (int mi = 0; mi < 2; mi++)
#pragma unroll
        for (int ni = 0; ni < 8; ni++)
#pragma unroll
            for (int j = 0; j < 4; j++) acc[mi][ni][j] = 0.f;

    // Prologue: issue tiles 0 and 1 into stages 0, 1.
#pragma unroll
    for (int p = 0; p < 2; p++) {
        const uint32_t sb2 = smb + p * BUF_W * 4;
#pragma unroll
        for (int it = 0; it < 4; it++) {
            uint32_t so = (lrow[it] * KW + lc[it] / 2) * 4;
            cp16(sb2 + so,              &A[(size_t)(bm + lrow[it]) * EMB + p * 64 + lc[it]]);
            cp16(sb2 + TILE_W * 4 + so, &B[(size_t)(bn + lrow[it]) * EMB + p * 64 + lc[it]]);
        }
        CP_COMMIT();
    }

    int stg = 0;                 // ks % 3
    for (int ks = 0; ks < 16; ks++) {
        if (ks < 15) CP_WAIT1(); else CP_WAIT0();
        __syncthreads();         // all warps done reading stage (ks-1)%3 == (ks+2)%3

        if (ks + 2 < 16) {
            int ns = stg + 2; if (ns >= 3) ns -= 3;
            const uint32_t sb2 = smb + ns * BUF_W * 4;
#pragma unroll
            for (int it = 0; it < 4; it++) {
                uint32_t so = (lrow[it] * KW + lc[it] / 2) * 4;
                cp16(sb2 + so,              &A[(size_t)(bm + lrow[it]) * EMB + (ks + 2) * 64 + lc[it]]);
                cp16(sb2 + TILE_W * 4 + so, &B[(size_t)(bn + lrow[it]) * EMB + (ks + 2) * 64 + lc[it]]);
            }
            CP_COMMIT();
        }

        const uint32_t* as = sm + stg * BUF_W + (wm * 32) * KW;
        const uint32_t* bs = sm + stg * BUF_W + TILE_W + (wn * 64) * KW;

#pragma unroll
        for (int kk = 0; kk < 4; kk++) {
            const int k0 = kk * 8;
            uint32_t af[2][4];
#pragma unroll
            for (int mi = 0; mi < 2; mi++) {
                int r = mi * 16 + g;
                af[mi][0] = as[(r    ) * KW + k0 + tig];
                af[mi][1] = as[(r + 8) * KW + k0 + tig];
                af[mi][2] = as[(r    ) * KW + k0 + 4 + tig];
                af[mi][3] = as[(r + 8) * KW + k0 + 4 + tig];
            }
#pragma unroll
            for (int ni = 0; ni < 8; ni++) {
                uint32_t bf[2];
                int nr = ni * 8 + g;
                bf[0] = bs[nr * KW + k0 + tig];
                bf[1] = bs[nr * KW + k0 + 4 + tig];
                mma_f16(acc[0][ni], af[0], bf);
                mma_f16(acc[1][ni], af[1], bf);
            }
        }
        if (++stg == 3) stg = 0;
    }

#pragma unroll
    for (int mi = 0; mi < 2; mi++) {
        int r0 = bm + wm * 32 + mi * 16 + g;
#pragma unroll
        for (int ni = 0; ni < 8; ni++) {
            int col = bn + wn * 64 + ni * 8 + 2 * tig;
            float b0 = 0.f, b1 = 0.f;
            if (bias) { b0 = bias[col]; b1 = bias[col + 1]; }
            float c0 = acc[mi][ni][0] + b0, c1 = acc[mi][ni][1] + b1;
            float c2 = acc[mi][ni][2] + b0, c3 = acc[mi][ni][3] + b1;
            if (OUTHALF) {
                __half* Ch = (__half*)Cptr;
                *(uint32_t*)&Ch[(size_t)r0 * EMB + col]       = pack_h2(c0, c1);
                *(uint32_t*)&Ch[(size_t)(r0 + 8) * EMB + col] = pack_h2(c2, c3);
            } else {
                float* Cf = (float*)Cptr;
                *(float2*)&Cf[(size_t)r0 * EMB + col]       = make_float2(c0, c1);
                *(float2*)&Cf[(size_t)(r0 + 8) * EMB + col] = make_float2(c2, c3);
            }
        }
    }
}

__global__ __launch_bounds__(256) void gemm_qkv(
    const __half* __restrict__ X,
    const __half* __restrict__ Wq, const __half* __restrict__ Wk,
    const __half* __restrict__ Wv,
    __half* __restrict__ Qo, __half* __restrict__ Ko, __half* __restrict__ Vo)
{
    extern __shared__ uint32_t sm[];
    const int wb = blockIdx.x >> 3;
    const int bn = (blockIdx.x & 7) * 128;
    const int bm = blockIdx.y * 128;
    const __half* B = (wb == 0) ? Wq : (wb == 1) ? Wk : Wv;
    __half*       C = (wb == 0) ? Qo : (wb == 1) ? Ko : Vo;
    gemm_h_body<true>(X, B, nullptr, C, bm, bn, sm);
}

__global__ __launch_bounds__(256) void gemm_out(
    const __half* __restrict__ A, const __half* __restrict__ W,
    const float* __restrict__ bias, float* __restrict__ C)
{
    extern __shared__ uint32_t sm[];
    gemm_h_body<false>(A, W, bias, C, blockIdx.y * 128, blockIdx.x * 128, sm);
}

// ---------------------------------------------------------------------------
// Flash attention (causal), fp16 mma + poly exp2. cp.async 3-stage K/V,
// ldmatrix fragments. Row stride AW=36 words.
// Smem: K stages [0,3*9216), V stages [3*9216,6*9216), P at 6*9216.
// ---------------------------------------------------------------------------
#define AW 36
#define KV_STAGE_B (64 * AW * 4)              // 9216
#define V_BASE_B   (3 * KV_STAGE_B)
#define PS_OFF_B   (6 * KV_STAGE_B)           // 55296
#define ATTN_SMEM  (PS_OFF_B + 128 * AW * 4)  // 73728

__global__ __launch_bounds__(256, 2) void attn_mma(
    const __half* __restrict__ Q, const __half* __restrict__ K,
    const __half* __restrict__ V, __half* __restrict__ O)
{
    extern __shared__ __align__(16) uint32_t smw[];
    uint32_t* PsW = smw + PS_OFF_B / 4;
    const uint32_t smb = (uint32_t)__cvta_generic_to_shared(smw);

    const int tid  = threadIdx.x;
    const int lane = tid & 31, w = tid >> 5;
    const int g    = lane >> 2, tig = lane & 3;
    const int qt   = 15 - blockIdx.x;
    const int bh   = blockIdx.y;
    const int b    = bh >> 4, h = bh & 15;
    const size_t base  = (size_t)b * TS * EMB + (size_t)h * HD;
    const int    qbase = qt * 128;
    const int    nkt   = 2 * qt + 2;

    const int lm_t = lane & 7, lm_sel = lane >> 3;

    // Per-thread load map (same for K and V): 2 x cp16 each.
    int krow[2], kc_[2];
#pragma unroll
    for (int it = 0; it < 2; it++) {
        int v = tid + it * 256;
        krow[it] = v >> 3; kc_[it] = v & 7;
    }

    // ---- Prologue: issue tiles 0 and 1 into stages 0, 1 (nkt >= 2 always).
#pragma unroll
    for (int p = 0; p < 2; p++) {
#pragma unroll
        for (int it = 0; it < 2; it++) {
            uint32_t so = (krow[it] * AW + kc_[it] * 4) * 4;
            const size_t gofs = base + (size_t)(p * 64 + krow[it]) * EMB + kc_[it] * 8;
            cp16(smb + p * KV_STAGE_B + so,          &K[gofs]);
            cp16(smb + V_BASE_B + p * KV_STAGE_B + so, &V[gofs]);
        }
        CP_COMMIT();
    }

    // ---- Stage Q tile into Ps, lift to fragments (per-warp rows only).
#pragma unroll
    for (int it = 0; it < 4; it++) {
        int v = tid + it * 256;
        int row = v >> 3, c = v & 7;
        uint4 t = *(const uint4*)&Q[base + (size_t)(qbase + row) * EMB + c * 8];
        *(uint4*)&PsW[row * AW + c * 4] = t;
    }
    __syncthreads();

    uint32_t qa[4][4];
    {
        const int r0 = w * 16 + g;
#pragma unroll
        for (int kc = 0; kc < 4; kc++) {
            qa[kc][0] = PsW[(r0    ) * AW + kc * 8 + tig];
            qa[kc][1] = PsW[(r0 + 8) * AW + kc * 8 + tig];
            qa[kc][2] = PsW[(r0    ) * AW + kc * 8 + 4 + tig];
            qa[kc][3] = PsW[(r0 + 8) * AW + kc * 8 + 4 + tig];
        }
    }

    float m0 = -1e30f, m1 = -1e30f, l0 = 0.f, l1 = 0.f;
    float o[8][4];
#pragma unroll
    for (int ni = 0; ni < 8; ni++)
#pragma unroll
        for (int j = 0; j < 4; j++) o[ni][j] = 0.f;

    const float scale2 = 0.125f * 1.44269504089f;
    const int qrow_max = qbase + w * 16 + 15;

    int stg = 0;   // kt % 3
    for (int kt = 0; kt < nkt; kt++) {
        if (kt < nkt - 1) CP_WAIT1(); else CP_WAIT0();
        __syncthreads();   // all warps done reading stage (kt-1)%3 == (kt+2)%3

        if (kt + 2 < nkt) {
            int ns = stg + 2; if (ns >= 3) ns -= 3;
#pragma unroll
            for (int it = 0; it < 2; it++) {
                uint32_t so = (krow[it] * AW + kc_[it] * 4) * 4;
                const size_t gofs = base + (size_t)((kt + 2) * 64 + krow[it]) * EMB + kc_[it] * 8;
                cp16(smb + ns * KV_STAGE_B + so,            &K[gofs]);
                cp16(smb + V_BASE_B + ns * KV_STAGE_B + so, &V[gofs]);
            }
            CP_COMMIT();
        }

        if (kt * 64 <= qrow_max) {
            const uint32_t KsS = smb + stg * KV_STAGE_B;
            const uint32_t VsS = smb + V_BASE_B + stg * KV_STAGE_B;

            float sc[8][4];
#pragma unroll
            for (int ni = 0; ni < 8; ni++)
                sc[ni][0] = sc[ni][1] = sc[ni][2] = sc[ni][3] = 0.f;
#pragma unroll
            for (int np = 0; np < 4; np++) {
#pragma unroll
                for (int kc = 0; kc < 4; kc++) {
                    int row  = np * 16 + ((lm_sel >> 1) << 3) + lm_t;
                    int hoff = kc * 16 + ((lm_sel & 1) << 3);
                    uint32_t b0, b1, b2, b3;
                    ldm_x4(b0, b1, b2, b3, KsS + row * (AW * 4) + hoff * 2);
                    uint32_t bfA[2] = {b0, b1}, bfB[2] = {b2, b3};
                    mma_f16(sc[2 * np],     qa[kc], bfA);
                    mma_f16(sc[2 * np + 1], qa[kc], bfB);
                }
            }

            const bool diag = (kt * 64 + 63 > qbase + w * 16);
            const int qg0 = qbase + w * 16 + g, qg1 = qg0 + 8;
#pragma unroll
            for (int ni = 0; ni < 8; ni++) {
#pragma unroll
                for (int j = 0; j < 4; j++) sc[ni][j] *= scale2;
                if (diag) {
                    int kg = kt * 64 + ni * 8 + 2 * tig;
                    if (kg     > qg0) sc[ni][0] = -1e30f;
                    if (kg + 1 > qg0) sc[ni][1] = -1e30f;
                    if (kg     > qg1) sc[ni][2] = -1e30f;
                    if (kg + 1 > qg1) sc[ni][3] = -1e30f;
                }
            }

            float rm0 = -1e30f, rm1 = -1e30f;
#pragma unroll
            for (int ni = 0; ni < 8; ni++) {
                rm0 = fmaxf(rm0, fmaxf(sc[ni][0], sc[ni][1]));
                rm1 = fmaxf(rm1, fmaxf(sc[ni][2], sc[ni][3]));
            }
            rm0 = qmax(rm0); rm1 = qmax(rm1);
            float mn0 = fmaxf(m0, rm0), mn1 = fmaxf(m1, rm1);
            float a0 = exp2p(m0 - mn0), a1 = exp2p(m1 - mn1);
            m0 = mn0; m1 = mn1;
#pragma unroll
            for (int ni = 0; ni < 8; ni++) {
                o[ni][0] *= a0; o[ni][1] *= a0;
                o[ni][2] *= a1; o[ni][3] *= a1;
            }
            float s0 = 0.f, s1 = 0.f;
            const int pr0 = w * 16 + g;
#pragma unroll
            for (int ni = 0; ni < 8; ni++) {
                float p0 = exp2p(sc[ni][0] - mn0);
                float p1 = exp2p(sc[ni][1] - mn0);
                float p2 = exp2p(sc[ni][2] - mn1);
                float p3 = exp2p(sc[ni][3] - mn1);
                s0 += p0 + p1; s1 += p2 + p3;
                PsW[(pr0    ) * AW + ni * 4 + tig] = pack_h2(p0, p1);
                PsW[(pr0 + 8) * AW + ni * 4 + tig] = pack_h2(p2, p3);
            }
            l0 = l0 * a0 + qsum(s0);
            l1 = l1 * a1 + qsum(s1);
            __syncwarp();

#pragma unroll
            for (int kc = 0; kc < 4; kc++) {
                uint32_t pa[4];
                pa[0] = PsW[(pr0    ) * AW + kc * 8 + tig];
                pa[1] = PsW[(pr0 + 8) * AW + kc * 8 + tig];
                pa[2] = PsW[(pr0    ) * AW + kc * 8 + 4 + tig];
                pa[3] = PsW[(pr0 + 8) * AW + kc * 8 + 4 + tig];
#pragma unroll
                for (int ndp = 0; ndp < 4; ndp++) {
                    int row  = kc * 16 + ((lm_sel & 1) << 3) + lm_t;
                    int hoff = ndp * 16 + ((lm_sel >> 1) << 3);
                    uint32_t b0, b1, b2, b3;
                    ldm_x4_t(b0, b1, b2, b3, VsS + row * (AW * 4) + hoff * 2);
                    uint32_t bfA[2] = {b0, b1}, bfB[2] = {b2, b3};
                    mma_f16(o[2 * ndp],     pa, bfA);
                    mma_f16(o[2 * ndp + 1], pa, bfB);
                }
            }
            __syncwarp();
        }
        if (++stg == 3) stg = 0;
    }

    const float inv0 = 1.f / l0, inv1 = 1.f / l1;
    const int q0 = qbase + w * 16 + g;
#pragma unroll
    for (int nd = 0; nd < 8; nd++) {
        int col = nd * 8 + 2 * tig;
        *(uint32_t*)&O[base + (size_t)q0 * EMB + col] =
            pack_h2(o[nd][0] * inv0, o[nd][1] * inv0);
        *(uint32_t*)&O[base + (size_t)(q0 + 8) * EMB + col] =
            pack_h2(o[nd][2] * inv1, o[nd][3] * inv1);
    }
}

// ---------------------------------------------------------------------------
extern "C" void kernel_launch(void* const* d_in, const int* in_sizes, int n_in,
                              void* d_out, int out_size)
{
    const float* x  = (const float*)d_in[0];
    // d_in[1] = mask (exact causal tril) -- applied analytically
    const float* Wq = (const float*)d_in[2];
    const float* Wk = (const float*)d_in[3];
    const float* Wv = (const float*)d_in[4];
    const float* Wo = (const float*)d_in[5];
    const float* bo = (const float*)d_in[6];
    float* out = (float*)d_out;

    __half *Qh, *Kh, *Vh, *Ah, *Xh, *Wqh, *Wkh, *Wvh, *Woh;
    cudaGetSymbolAddress((void**)&Qh, g_Qh);
    cudaGetSymbolAddress((void**)&Kh, g_Kh);
    cudaGetSymbolAddress((void**)&Vh, g_Vh);
    cudaGetSymbolAddress((void**)&Ah, g_Ah);
    cudaGetSymbolAddress((void**)&Xh, g_Xh);
    cudaGetSymbolAddress((void**)&Wqh, g_Wqh);
    cudaGetSymbolAddress((void**)&Wkh, g_Wkh);
    cudaGetSymbolAddress((void**)&Wvh, g_Wvh);
    cudaGetSymbolAddress((void**)&Woh, g_Woh);

    cudaFuncSetAttribute(gemm_qkv, cudaFuncAttributeMaxDynamicSharedMemorySize, GEMM_SMEM);
    cudaFuncSetAttribute(gemm_out, cudaFuncAttributeMaxDynamicSharedMemorySize, GEMM_SMEM);
    cudaFuncSetAttribute(attn_mma, cudaFuncAttributeMaxDynamicSharedMemorySize, ATTN_SMEM);

    const size_t total = (size_t)ROWS * EMB + 4 * (size_t)EMB * EMB;
    cvt_all<<<(int)(total / (256 * 8)), 256>>>(x, Wq, Wk, Wv, Wo,
                                               Xh, Wqh, Wkh, Wvh, Woh);

    dim3 qkvgrid(24, ROWS / 128);       // (24, 32)
    gemm_qkv<<<qkvgrid, 256, GEMM_SMEM>>>(Xh, Wqh, Wkh, Wvh, Qh, Kh, Vh);

    dim3 agrid(16, 2 * NHEADS);         // (16, 32)
    attn_mma<<<agrid, 256, ATTN_SMEM>>>(Qh, Kh, Vh, Ah);

    dim3 ogrid(EMB / 128, ROWS / 128);  // (8, 32)
    gemm_out<<<ogrid, 256, GEMM_SMEM>>>(Ah, Woh, bo, out);
}

// round 14
// speedup vs baseline: 1.4965x; 1.4965x over previous
#include <cuda_runtime.h>
#include <cuda_bf16.h>
#include <cuda_fp16.h>
#include <cstdint>

// Problem: MaskedSelfAttention  B=2, S=2048, E=1024, H=16, D=64, causal.
// R14: revert to R12's 2-stage pipelines (3-stage smem cost 3->2 CTAs/SM =
//      the R13 regression). GEMM fragment loads switch scalar LDS -> ldmatrix
//      (4x fewer issue slots). rel_err canary 6.582877e-4.

#define TS   2048
#define EMB  1024
#define NHEADS 16
#define HD   64
#define ROWS (2*TS)

__device__ __half g_Qh[ROWS*EMB];
__device__ __half g_Kh[ROWS*EMB];
__device__ __half g_Vh[ROWS*EMB];
__device__ __half g_Ah[ROWS*EMB];
__device__ __half g_Xh[ROWS*EMB];
__device__ __half g_Wqh[EMB*EMB];
__device__ __half g_Wkh[EMB*EMB];
__device__ __half g_Wvh[EMB*EMB];
__device__ __half g_Woh[EMB*EMB];

__device__ __forceinline__ void mma_f16(float* d, const uint32_t* a, const uint32_t* b) {
    asm volatile(
        "mma.sync.aligned.m16n8k16.row.col.f32.f16.f16.f32 "
        "{%0,%1,%2,%3}, {%4,%5,%6,%7}, {%8,%9}, {%0,%1,%2,%3};"
        : "+f"(d[0]), "+f"(d[1]), "+f"(d[2]), "+f"(d[3])
        : "r"(a[0]), "r"(a[1]), "r"(a[2]), "r"(a[3]), "r"(b[0]), "r"(b[1]));
}

__device__ __forceinline__ uint32_t pack_h2(float x, float y) {
    __half2 h = __floats2half2_rn(x, y);
    return *(uint32_t*)&h;
}

__device__ __forceinline__ void ldm_x4(uint32_t& r0, uint32_t& r1,
                                       uint32_t& r2, uint32_t& r3, uint32_t addr) {
    asm volatile("ldmatrix.sync.aligned.m8n8.x4.shared.b16 {%0,%1,%2,%3}, [%4];"
        : "=r"(r0), "=r"(r1), "=r"(r2), "=r"(r3) : "r"(addr));
}
__device__ __forceinline__ void ldm_x4_t(uint32_t& r0, uint32_t& r1,
                                         uint32_t& r2, uint32_t& r3, uint32_t addr) {
    asm volatile("ldmatrix.sync.aligned.m8n8.x4.trans.shared.b16 {%0,%1,%2,%3}, [%4];"
        : "=r"(r0), "=r"(r1), "=r"(r2), "=r"(r3) : "r"(addr));
}

__device__ __forceinline__ void cp16(uint32_t saddr, const void* g) {
    asm volatile("cp.async.cg.shared.global [%0], [%1], 16;" :: "r"(saddr), "l"(g));
}
#define CP_COMMIT() asm volatile("cp.async.commit_group;" ::: "memory")
#define CP_WAIT0()  asm volatile("cp.async.wait_group 0;" ::: "memory")

// exp2 on the FMA/ALU pipes (no MUFU).
__device__ __forceinline__ float exp2p(float d) {
    d = fmaxf(d, -120.f);
    float t = d + 12582912.f;
    float f = d - (t - 12582912.f);
    uint32_t e = (__float_as_uint(t) + (127u - 0x4B400000u)) << 23;
    float p = 1.3333558146e-3f;
    p = fmaf(p, f, 9.6181291076e-3f);
    p = fmaf(p, f, 5.5504108665e-2f);
    p = fmaf(p, f, 2.4022650696e-1f);
    p = fmaf(p, f, 6.9314718056e-1f);
    p = fmaf(p, f, 1.0f);
    return p * __uint_as_float(e);
}

__device__ __forceinline__ float qmax(float v) {
    v = fmaxf(v, __shfl_xor_sync(0xffffffffu, v, 1));
    v = fmaxf(v, __shfl_xor_sync(0xffffffffu, v, 2));
    return v;
}
__device__ __forceinline__ float qsum(float v) {
    v += __shfl_xor_sync(0xffffffffu, v, 1);
    v += __shfl_xor_sync(0xffffffffu, v, 2);
    return v;
}

// ---------------------------------------------------------------------------
// Prepass: convert x (4M) + 4 weights (1M each) fp32 -> fp16. 8 elems/thread.
// ---------------------------------------------------------------------------
__global__ __launch_bounds__(256) void cvt_all(
    const float* __restrict__ X,
    const float* __restrict__ Wq, const float* __restrict__ Wk,
    const float* __restrict__ Wv, const float* __restrict__ Wo,
    __half* __restrict__ Xh, __half* __restrict__ Wqh, __half* __restrict__ Wkh,
    __half* __restrict__ Wvh, __half* __restrict__ Woh)
{
    size_t i = ((size_t)blockIdx.x * 256 + threadIdx.x) * 8;
    const float* src; __half* dst; size_t off;
    const size_t NX = (size_t)ROWS * EMB, NW = (size_t)EMB * EMB;
    if (i < NX)               { src = X;  dst = Xh;  off = i; }
    else if (i < NX + NW)     { src = Wq; dst = Wqh; off = i - NX; }
    else if (i < NX + 2*NW)   { src = Wk; dst = Wkh; off = i - NX - NW; }
    else if (i < NX + 3*NW)   { src = Wv; dst = Wvh; off = i - NX - 2*NW; }
    else                      { src = Wo; dst = Woh; off = i - NX - 3*NW; }
    float4 a = *(const float4*)&src[off];
    float4 b = *(const float4*)&src[off + 4];
    uint4 u = make_uint4(pack_h2(a.x, a.y), pack_h2(a.z, a.w),
                         pack_h2(b.x, b.y), pack_h2(b.z, b.w));
    *(uint4*)&dst[off] = u;
}

// ---------------------------------------------------------------------------
// fp16 GEMM: CTA 128x128, BK=64, 8 warps, cp.async 2-stage (R12 structure),
// fragment loads via ldmatrix.x4. Row stride KW=36 words (conflict-free).
// ---------------------------------------------------------------------------
#define KW 36
#define TILE_W (128 * KW)
#define BUF_W  (2 * TILE_W)
#define GEMM_SMEM (2 * BUF_W * 4)   // 73728 B -> 3 CTAs/SM

template <bool OUTHALF>
__device__ __forceinline__ void gemm_h_body(
    const __half* __restrict__ A, const __half* __restrict__ B,
    const float* __restrict__ bias, void* __restrict__ Cptr,
    int bm, int bn, uint32_t* sm)
{
    const uint32_t smb = (uint32_t)__cvta_generic_to_shared(sm);
    const int tid  = threadIdx.x;
    const int lane = tid & 31, warp = tid >> 5;
    const int g    = lane >> 2, tig = lane & 3;
    const int wm   = warp >> 1, wn = warp & 1;
    const int lm_t = lane & 7, lm_sel = lane >> 3;
    // ldmatrix address row/col selectors (R11-proven pattern):
    const int lmr = ((lm_sel >> 1) << 3) + lm_t;   // row within 16-row tile
    const int lmh = (lm_sel & 1) << 3;             // half offset within 16 halves

    int lrow[4], lc[4];
#pragma unroll
    for (int it = 0; it < 4; it++) {
        int v = tid + it * 256;
        lrow[it] = v >> 3;
        lc[it]   = (v & 7) * 8;
    }

    float acc[2][8][4];
#pragma unroll
    for (int mi = 0; mi < 2; mi++)
#pragma unroll
        for (int ni = 0; ni < 8; ni++)
#pragma unroll
            for (int j = 0; j < 4; j++) acc[mi][ni][j] = 0.f;

    // Prologue: issue cp.async for tile 0 -> stage 0.
#pragma unroll
    for (int it = 0; it < 4; it++) {
        uint32_t so = (lrow[it] * KW + lc[it] / 2) * 4;
        cp16(smb + so,              &A[(size_t)(bm + lrow[it]) * EMB + lc[it]]);
        cp16(smb + TILE_W * 4 + so, &B[(size_t)(bn + lrow[it]) * EMB + lc[it]]);
    }
    CP_COMMIT();

    for (int ks = 0; ks < 16; ks++) {
        const int cur = ks & 1;
        CP_WAIT0();
        __syncthreads();

        if (ks + 1 < 16) {
            const uint32_t sb2 = smb + (cur ^ 1) * BUF_W * 4;
#pragma unroll
            for (int it = 0; it < 4; it++) {
                uint32_t so = (lrow[it] * KW + lc[it] / 2) * 4;
                cp16(sb2 + so,              &A[(size_t)(bm + lrow[it]) * EMB + (ks + 1) * 64 + lc[it]]);
                cp16(sb2 + TILE_W * 4 + so, &B[(size_t)(bn + lrow[it]) * EMB + (ks + 1) * 64 + lc[it]]);
            }
            CP_COMMIT();
        }

        const uint32_t Ab = smb + cur * BUF_W * 4 + (wm * 32) * (KW * 4);
        const uint32_t Bb = smb + cur * BUF_W * 4 + TILE_W * 4 + (wn * 64) * (KW * 4);

        // 4 k16 steps per BK=64; fragments via ldmatrix.x4.
#pragma unroll
        for (int kk = 0; kk < 4; kk++) {
            const int h0 = kk * 16;   // half offset of this k16 step
            uint32_t af[2][4];
#pragma unroll
            for (int mi = 0; mi < 2; mi++) {
                uint32_t r0, r1, r2, r3;
                ldm_x4(r0, r1, r2, r3,
                       Ab + (mi * 16 + lmr) * (KW * 4) + (h0 + lmh) * 2);
                // ldm returns {m0-7k0-7, m0-7k8-15, m8-15k0-7, m8-15k8-15};
                // A-operand order is {a0=r0, a1=r2, a2=r1, a3=r3}.
                af[mi][0] = r0; af[mi][1] = r2; af[mi][2] = r1; af[mi][3] = r3;
            }
#pragma unroll
            for (int nb = 0; nb < 4; nb++) {
                uint32_t b0, b1, b2, b3;
                ldm_x4(b0, b1, b2, b3,
                       Bb + (nb * 16 + lmr) * (KW * 4) + (h0 + lmh) * 2);
                uint32_t bfA[2] = {b0, b1}, bfB[2] = {b2, b3};
                mma_f16(acc[0][2 * nb],     af[0], bfA);
                mma_f16(acc[1][2 * nb],     af[1], bfA);
                mma_f16(acc[0][2 * nb + 1], af[0], bfB);
                mma_f16(acc[1][2 * nb + 1], af[1], bfB);
            }
        }
    }

#pragma unroll
    for (int mi = 0; mi < 2; mi++) {
        int r0 = bm + wm * 32 + mi * 16 + g;
#pragma unroll
        for (int ni = 0; ni < 8; ni++) {
            int col = bn + wn * 64 + ni * 8 + 2 * tig;
            float b0 = 0.f, b1 = 0.f;
            if (bias) { b0 = bias[col]; b1 = bias[col + 1]; }
            float c0 = acc[mi][ni][0] + b0, c1 = acc[mi][ni][1] + b1;
            float c2 = acc[mi][ni][2] + b0, c3 = acc[mi][ni][3] + b1;
            if (OUTHALF) {
                __half* Ch = (__half*)Cptr;
                *(uint32_t*)&Ch[(size_t)r0 * EMB + col]       = pack_h2(c0, c1);
                *(uint32_t*)&Ch[(size_t)(r0 + 8) * EMB + col] = pack_h2(c2, c3);
            } else {
                float* Cf = (float*)Cptr;
                *(float2*)&Cf[(size_t)r0 * EMB + col]       = make_float2(c0, c1);
                *(float2*)&Cf[(size_t)(r0 + 8) * EMB + col] = make_float2(c2, c3);
            }
        }
    }
}

__global__ __launch_bounds__(256) void gemm_qkv(
    const __half* __restrict__ X,
    const __half* __restrict__ Wq, const __half* __restrict__ Wk,
    const __half* __restrict__ Wv,
    __half* __restrict__ Qo, __half* __restrict__ Ko, __half* __restrict__ Vo)
{
    extern __shared__ uint32_t sm[];
    const int wb = blockIdx.x >> 3;
    const int bn = (blockIdx.x & 7) * 128;
    const int bm = blockIdx.y * 128;
    const __half* B = (wb == 0) ? Wq : (wb == 1) ? Wk : Wv;
    __half*       C = (wb == 0) ? Qo : (wb == 1) ? Ko : Vo;
    gemm_h_body<true>(X, B, nullptr, C, bm, bn, sm);
}

__global__ __launch_bounds__(256) void gemm_out(
    const __half* __restrict__ A, const __half* __restrict__ W,
    const float* __restrict__ bias, float* __restrict__ C)
{
    extern __shared__ uint32_t sm[];
    gemm_h_body<false>(A, W, bias, C, blockIdx.y * 128, blockIdx.x * 128, sm);
}

// ---------------------------------------------------------------------------
// Flash attention (causal), fp16 mma + poly exp2. cp.async 2-stage K/V,
// ldmatrix fragments. Row stride AW=36 words. (R12 exact, proven.)
// ---------------------------------------------------------------------------
#define AW 36
#define KV_STAGE_B (64 * AW * 4)
#define PS_OFF_B   (4 * KV_STAGE_B)
#define ATTN_SMEM  (PS_OFF_B + 128 * AW * 4)   // 55296

__global__ __launch_bounds__(256, 2) void attn_mma(
    const __half* __restrict__ Q, const __half* __restrict__ K,
    const __half* __restrict__ V, __half* __restrict__ O)
{
    extern __shared__ __align__(16) uint32_t smw[];
    uint32_t* PsW = smw + PS_OFF_B / 4;
    const uint32_t smb = (uint32_t)__cvta_generic_to_shared(smw);

    const int tid  = threadIdx.x;
    const int lane = tid & 31, w = tid >> 5;
    const int g    = lane >> 2, tig = lane & 3;
    const int qt   = 15 - blockIdx.x;
    const int bh   = blockIdx.y;
    const int b    = bh >> 4, h = bh & 15;
    const size_t base  = (size_t)b * TS * EMB + (size_t)h * HD;
    const int    qbase = qt * 128;
    const int    nkt   = 2 * qt + 2;

    const int lm_t = lane & 7, lm_sel = lane >> 3;

    // ---- Prologue: issue cp.async for tile 0 -> stage 0.
    {
#pragma unroll
        for (int it = 0; it < 2; it++) {
            int v = tid + it * 256;
            int row = v >> 3, c = v & 7;
            cp16(smb + (row * AW + c * 4) * 4,
                 &K[base + (size_t)(row) * EMB + c * 8]);
        }
#pragma unroll
        for (int it = 0; it < 2; it++) {
            int v = tid + it * 256;
            int row = v >> 3, c = v & 7;
            cp16(smb + 2 * KV_STAGE_B + (row * AW + c * 4) * 4,
                 &V[base + (size_t)(row) * EMB + c * 8]);
        }
        CP_COMMIT();
    }

    // ---- Stage Q tile into Ps, lift to fragments.
#pragma unroll
    for (int it = 0; it < 4; it++) {
        int v = tid + it * 256;
        int row = v >> 3, c = v & 7;
        uint4 t = *(const uint4*)&Q[base + (size_t)(qbase + row) * EMB + c * 8];
        *(uint4*)&PsW[row * AW + c * 4] = t;
    }
    __syncthreads();

    uint32_t qa[4][4];
    {
        const int r0 = w * 16 + g;
#pragma unroll
        for (int kc = 0; kc < 4; kc++) {
            qa[kc][0] = PsW[(r0    ) * AW + kc * 8 + tig];
            qa[kc][1] = PsW[(r0 + 8) * AW + kc * 8 + tig];
            qa[kc][2] = PsW[(r0    ) * AW + kc * 8 + 4 + tig];
            qa[kc][3] = PsW[(r0 + 8) * AW + kc * 8 + 4 + tig];
        }
    }

    float m0 = -1e30f, m1 = -1e30f, l0 = 0.f, l1 = 0.f;
    float o[8][4];
#pragma unroll
    for (int ni = 0; ni < 8; ni++)
#pragma unroll
        for (int j = 0; j < 4; j++) o[ni][j] = 0.f;

    const float scale2 = 0.125f * 1.44269504089f;
    const int qrow_max = qbase + w * 16 + 15;

    for (int kt = 0; kt < nkt; kt++) {
        CP_WAIT0();
        __syncthreads();

        if (kt + 1 < nkt) {
            const int ns = (kt + 1) & 1;
#pragma unroll
            for (int it = 0; it < 2; it++) {
                int v = tid + it * 256;
                int row = v >> 3, c = v & 7;
                cp16(smb + ns * KV_STAGE_B + (row * AW + c * 4) * 4,
                     &K[base + (size_t)((kt + 1) * 64 + row) * EMB + c * 8]);
            }
#pragma unroll
            for (int it = 0; it < 2; it++) {
                int v = tid + it * 256;
                int row = v >> 3, c = v & 7;
                cp16(smb + 2 * KV_STAGE_B + ns * KV_STAGE_B + (row * AW + c * 4) * 4,
                     &V[base + (size_t)((kt + 1) * 64 + row) * EMB + c * 8]);
            }
            CP_COMMIT();
        }

        if (kt * 64 > qrow_max) continue;

        const uint32_t KsS = smb + (kt & 1) * KV_STAGE_B;
        const uint32_t VsS = smb + 2 * KV_STAGE_B + (kt & 1) * KV_STAGE_B;

        float sc[8][4];
#pragma unroll
        for (int ni = 0; ni < 8; ni++)
            sc[ni][0] = sc[ni][1] = sc[ni][2] = sc[ni][3] = 0.f;
#pragma unroll
        for (int np = 0; np < 4; np++) {
#pragma unroll
            for (int kc = 0; kc < 4; kc++) {
                int row  = np * 16 + ((lm_sel >> 1) << 3) + lm_t;
                int hoff = kc * 16 + ((lm_sel & 1) << 3);
                uint32_t b0, b1, b2, b3;
                ldm_x4(b0, b1, b2, b3, KsS + row * (AW * 4) + hoff * 2);
                uint32_t bfA[2] = {b0, b1}, bfB[2] = {b2, b3};
                mma_f16(sc[2 * np],     qa[kc], bfA);
                mma_f16(sc[2 * np + 1], qa[kc], bfB);
            }
        }

        const bool diag = (kt * 64 + 63 > qbase + w * 16);
        const int qg0 = qbase + w * 16 + g, qg1 = qg0 + 8;
#pragma unroll
        for (int ni = 0; ni < 8; ni++) {
#pragma unroll
            for (int j = 0; j < 4; j++) sc[ni][j] *= scale2;
            if (diag) {
                int kg = kt * 64 + ni * 8 + 2 * tig;
                if (kg     > qg0) sc[ni][0] = -1e30f;
                if (kg + 1 > qg0) sc[ni][1] = -1e30f;
                if (kg     > qg1) sc[ni][2] = -1e30f;
                if (kg + 1 > qg1) sc[ni][3] = -1e30f;
            }
        }

        float rm0 = -1e30f, rm1 = -1e30f;
#pragma unroll
        for (int ni = 0; ni < 8; ni++) {
            rm0 = fmaxf(rm0, fmaxf(sc[ni][0], sc[ni][1]));
            rm1 = fmaxf(rm1, fmaxf(sc[ni][2], sc[ni][3]));
        }
        rm0 = qmax(rm0); rm1 = qmax(rm1);
        float mn0 = fmaxf(m0, rm0), mn1 = fmaxf(m1, rm1);
        float a0 = exp2p(m0 - mn0), a1 = exp2p(m1 - mn1);
        m0 = mn0; m1 = mn1;
#pragma unroll
        for (int ni = 0; ni < 8; ni++) {
            o[ni][0] *= a0; o[ni][1] *= a0;
            o[ni][2] *= a1; o[ni][3] *= a1;
        }
        float s0 = 0.f, s1 = 0.f;
        const int pr0 = w * 16 + g;
#pragma unroll
        for (int ni = 0; ni < 8; ni++) {
            float p0 = exp2p(sc[ni][0] - mn0);
            float p1 = exp2p(sc[ni][1] - mn0);
            float p2 = exp2p(sc[ni][2] - mn1);
            float p3 = exp2p(sc[ni][3] - mn1);
            s0 += p0 + p1; s1 += p2 + p3;
            PsW[(pr0    ) * AW + ni * 4 + tig] = pack_h2(p0, p1);
            PsW[(pr0 + 8) * AW + ni * 4 + tig] = pack_h2(p2, p3);
        }
        l0 = l0 * a0 + qsum(s0);
        l1 = l1 * a1 + qsum(s1);
        __syncwarp();

#pragma unroll
        for (int kc = 0; kc < 4; kc++) {
            uint32_t pa[4];
            pa[0] = PsW[(pr0    ) * AW + kc * 8 + tig];
            pa[1] = PsW[(pr0 + 8) * AW + kc * 8 + tig];
            pa[2] = PsW[(pr0    ) * AW + kc * 8 + 4 + tig];
            pa[3] = PsW[(pr0 + 8) * AW + kc * 8 + 4 + tig];
#pragma unroll
            for (int ndp = 0; ndp < 4; ndp++) {
                int row  = kc * 16 + ((lm_sel & 1) << 3) + lm_t;
                int hoff = ndp * 16 + ((lm_sel >> 1) << 3);
                uint32_t b0, b1, b2, b3;
                ldm_x4_t(b0, b1, b2, b3, VsS + row * (AW * 4) + hoff * 2);
                uint32_t bfA[2] = {b0, b1}, bfB[2] = {b2, b3};
                mma_f16(o[2 * ndp],     pa, bfA);
                mma_f16(o[2 * ndp + 1], pa, bfB);
            }
        }
        __syncwarp();
    }

    const float inv0 = 1.f / l0, inv1 = 1.f / l1;
    const int q0 = qbase + w * 16 + g;
#pragma unroll
    for (int nd = 0; nd < 8; nd++) {
        int col = nd * 8 + 2 * tig;
        *(uint32_t*)&O[base + (size_t)q0 * EMB + col] =
            pack_h2(o[nd][0] * inv0, o[nd][1] * inv0);
        *(uint32_t*)&O[base + (size_t)(q0 + 8) * EMB + col] =
            pack_h2(o[nd][2] * inv1, o[nd][3] * inv1);
    }
}

// ---------------------------------------------------------------------------
extern "C" void kernel_launch(void* const* d_in, const int* in_sizes, int n_in,
                              void* d_out, int out_size)
{
    const float* x  = (const float*)d_in[0];
    // d_in[1] = mask (exact causal tril) -- applied analytically
    const float* Wq = (const float*)d_in[2];
    const float* Wk = (const float*)d_in[3];
    const float* Wv = (const float*)d_in[4];
    const float* Wo = (const float*)d_in[5];
    const float* bo = (const float*)d_in[6];
    float* out = (float*)d_out;

    __half *Qh, *Kh, *Vh, *Ah, *Xh, *Wqh, *Wkh, *Wvh, *Woh;
    cudaGetSymbolAddress((void**)&Qh, g_Qh);
    cudaGetSymbolAddress((void**)&Kh, g_Kh);
    cudaGetSymbolAddress((void**)&Vh, g_Vh);
    cudaGetSymbolAddress((void**)&Ah, g_Ah);
    cudaGetSymbolAddress((void**)&Xh, g_Xh);
    cudaGetSymbolAddress((void**)&Wqh, g_Wqh);
    cudaGetSymbolAddress((void**)&Wkh, g_Wkh);
    cudaGetSymbolAddress((void**)&Wvh, g_Wvh);
    cudaGetSymbolAddress((void**)&Woh, g_Woh);

    cudaFuncSetAttribute(gemm_qkv, cudaFuncAttributeMaxDynamicSharedMemorySize, GEMM_SMEM);
    cudaFuncSetAttribute(gemm_out, cudaFuncAttributeMaxDynamicSharedMemorySize, GEMM_SMEM);
    cudaFuncSetAttribute(attn_mma, cudaFuncAttributeMaxDynamicSharedMemorySize, ATTN_SMEM);

    const size_t total = (size_t)ROWS * EMB + 4 * (size_t)EMB * EMB;
    cvt_all<<<(int)(total / (256 * 8)), 256>>>(x, Wq, Wk, Wv, Wo,
                                               Xh, Wqh, Wkh, Wvh, Woh);

    dim3 qkvgrid(24, ROWS / 128);       // (24, 32)
    gemm_qkv<<<qkvgrid, 256, GEMM_SMEM>>>(Xh, Wqh, Wkh, Wvh, Qh, Kh, Vh);

    dim3 agrid(16, 2 * NHEADS);         // (16, 32)
    attn_mma<<<agrid, 256, ATTN_SMEM>>>(Qh, Kh, Vh, Ah);

    dim3 ogrid(EMB / 128, ROWS / 128);  // (8, 32)
    gemm_out<<<ogrid, 256, GEMM_SMEM>>>(Ah, Woh, bo, out);
}

// round 16
// speedup vs baseline: 1.5590x; 1.0418x over previous
#include <cuda_runtime.h>
#include <cuda_bf16.h>
#include <cuda_fp16.h>
#include <cstdint>

// Problem: MaskedSelfAttention  B=2, S=2048, E=1024, H=16, D=64, causal.
// R16 (= R15 resubmit; prior round hit a transient "device busy" infra error):
//      GEMMs = R12 scalar-LDS bodies (proven). Attention: P stays in registers
//      (score C-frag == PV A-frag layout), deleting the P smem round-trip +
//      syncwarps. Bit-identical math -> rel_err canary 6.582877e-4.

#define TS   2048
#define EMB  1024
#define NHEADS 16
#define HD   64
#define ROWS (2*TS)

__device__ __half g_Qh[ROWS*EMB];
__device__ __half g_Kh[ROWS*EMB];
__device__ __half g_Vh[ROWS*EMB];
__device__ __half g_Ah[ROWS*EMB];
__device__ __half g_Xh[ROWS*EMB];
__device__ __half g_Wqh[EMB*EMB];
__device__ __half g_Wkh[EMB*EMB];
__device__ __half g_Wvh[EMB*EMB];
__device__ __half g_Woh[EMB*EMB];

__device__ __forceinline__ void mma_f16(float* d, const uint32_t* a, const uint32_t* b) {
    asm volatile(
        "mma.sync.aligned.m16n8k16.row.col.f32.f16.f16.f32 "
        "{%0,%1,%2,%3}, {%4,%5,%6,%7}, {%8,%9}, {%0,%1,%2,%3};"
        : "+f"(d[0]), "+f"(d[1]), "+f"(d[2]), "+f"(d[3])
        : "r"(a[0]), "r"(a[1]), "r"(a[2]), "r"(a[3]), "r"(b[0]), "r"(b[1]));
}

__device__ __forceinline__ uint32_t pack_h2(float x, float y) {
    __half2 h = __floats2half2_rn(x, y);
    return *(uint32_t*)&h;
}

__device__ __forceinline__ void ldm_x4(uint32_t& r0, uint32_t& r1,
                                       uint32_t& r2, uint32_t& r3, uint32_t addr) {
    asm volatile("ldmatrix.sync.aligned.m8n8.x4.shared.b16 {%0,%1,%2,%3}, [%4];"
        : "=r"(r0), "=r"(r1), "=r"(r2), "=r"(r3) : "r"(addr));
}
__device__ __forceinline__ void ldm_x4_t(uint32_t& r0, uint32_t& r1,
                                         uint32_t& r2, uint32_t& r3, uint32_t addr) {
    asm volatile("ldmatrix.sync.aligned.m8n8.x4.trans.shared.b16 {%0,%1,%2,%3}, [%4];"
        : "=r"(r0), "=r"(r1), "=r"(r2), "=r"(r3) : "r"(addr));
}

__device__ __forceinline__ void cp16(uint32_t saddr, const void* g) {
    asm volatile("cp.async.cg.shared.global [%0], [%1], 16;" :: "r"(saddr), "l"(g));
}
#define CP_COMMIT() asm volatile("cp.async.commit_group;" ::: "memory")
#define CP_WAIT0()  asm volatile("cp.async.wait_group 0;" ::: "memory")

// exp2 on the FMA/ALU pipes (no MUFU).
__device__ __forceinline__ float exp2p(float d) {
    d = fmaxf(d, -120.f);
    float t = d + 12582912.f;
    float f = d - (t - 12582912.f);
    uint32_t e = (__float_as_uint(t) + (127u - 0x4B400000u)) << 23;
    float p = 1.3333558146e-3f;
    p = fmaf(p, f, 9.6181291076e-3f);
    p = fmaf(p, f, 5.5504108665e-2f);
    p = fmaf(p, f, 2.4022650696e-1f);
    p = fmaf(p, f, 6.9314718056e-1f);
    p = fmaf(p, f, 1.0f);
    return p * __uint_as_float(e);
}

__device__ __forceinline__ float qmax(float v) {
    v = fmaxf(v, __shfl_xor_sync(0xffffffffu, v, 1));
    v = fmaxf(v, __shfl_xor_sync(0xffffffffu, v, 2));
    return v;
}
__device__ __forceinline__ float qsum(float v) {
    v += __shfl_xor_sync(0xffffffffu, v, 1);
    v += __shfl_xor_sync(0xffffffffu, v, 2);
    return v;
}

// ---------------------------------------------------------------------------
// Prepass: convert x (4M) + 4 weights (1M each) fp32 -> fp16. 8 elems/thread.
// ---------------------------------------------------------------------------
__global__ __launch_bounds__(256) void cvt_all(
    const float* __restrict__ X,
    const float* __restrict__ Wq, const float* __restrict__ Wk,
    const float* __restrict__ Wv, const float* __restrict__ Wo,
    __half* __restrict__ Xh, __half* __restrict__ Wqh, __half* __restrict__ Wkh,
    __half* __restrict__ Wvh, __half* __restrict__ Woh)
{
    size_t i = ((size_t)blockIdx.x * 256 + threadIdx.x) * 8;
    const float* src; __half* dst; size_t off;
    const size_t NX = (size_t)ROWS * EMB, NW = (size_t)EMB * EMB;
    if (i < NX)               { src = X;  dst = Xh;  off = i; }
    else if (i < NX + NW)     { src = Wq; dst = Wqh; off = i - NX; }
    else if (i < NX + 2*NW)   { src = Wk; dst = Wkh; off = i - NX - NW; }
    else if (i < NX + 3*NW)   { src = Wv; dst = Wvh; off = i - NX - 2*NW; }
    else                      { src = Wo; dst = Woh; off = i - NX - 3*NW; }
    float4 a = *(const float4*)&src[off];
    float4 b = *(const float4*)&src[off + 4];
    uint4 u = make_uint4(pack_h2(a.x, a.y), pack_h2(a.z, a.w),
                         pack_h2(b.x, b.y), pack_h2(b.z, b.w));
    *(uint4*)&dst[off] = u;
}

// ---------------------------------------------------------------------------
// fp16 GEMM (R12 proven): CTA 128x128, BK=64, 8 warps, cp.async 2-stage,
// scalar-LDS fragment loads (immediate offsets). KW=36 conflict-free.
// ---------------------------------------------------------------------------
#define KW 36
#define TILE_W (128 * KW)
#define BUF_W  (2 * TILE_W)
#define GEMM_SMEM (2 * BUF_W * 4)   // 73728 B

template <bool OUTHALF>
__device__ __forceinline__ void gemm_h_body(
    const __half* __restrict__ A, const __half* __restrict__ B,
    const float* __restrict__ bias, void* __restrict__ Cptr,
    int bm, int bn, uint32_t* sm)
{
    const uint32_t smb = (uint32_t)__cvta_generic_to_shared(sm);
    const int tid  = threadIdx.x;
    const int lane = tid & 31, warp = tid >> 5;
    const int g    = lane >> 2, tig = lane & 3;
    const int wm   = warp >> 1, wn = warp & 1;

    int lrow[4], lc[4];
#pragma unroll
    for (int it = 0; it < 4; it++) {
        int v = tid + it * 256;
        lrow[it] = v >> 3;
        lc[it]   = (v & 7) * 8;
    }

    float acc[2][8][4];
#pragma unroll
    for (int mi = 0; mi < 2; mi++)
#pragma unroll
        for (int ni = 0; ni < 8; ni++)
#pragma unroll
            for (int j = 0; j < 4; j++) acc[mi][ni][j] = 0.f;

    // Prologue: issue cp.async for tile 0 -> stage 0.
#pragma unroll
    for (int it = 0; it < 4; it++) {
        uint32_t so = (lrow[it] * KW + lc[it] / 2) * 4;
        cp16(smb + so,              &A[(size_t)(bm + lrow[it]) * EMB + lc[it]]);
        cp16(smb + TILE_W * 4 + so, &B[(size_t)(bn + lrow[it]) * EMB + lc[it]]);
    }
    CP_COMMIT();

    for (int ks = 0; ks < 16; ks++) {
        const int cur = ks & 1;
        CP_WAIT0();
        __syncthreads();

        if (ks + 1 < 16) {
            const uint32_t sb2 = smb + (cur ^ 1) * BUF_W * 4;
#pragma unroll
            for (int it = 0; it < 4; it++) {
                uint32_t so = (lrow[it] * KW + lc[it] / 2) * 4;
                cp16(sb2 + so,              &A[(size_t)(bm + lrow[it]) * EMB + (ks + 1) * 64 + lc[it]]);
                cp16(sb2 + TILE_W * 4 + so, &B[(size_t)(bn + lrow[it]) * EMB + (ks + 1) * 64 + lc[it]]);
            }
            CP_COMMIT();
        }

        const uint32_t* as = sm + cur * BUF_W + (wm * 32) * KW;
        const uint32_t* bs = sm + cur * BUF_W + TILE_W + (wn * 64) * KW;

#pragma unroll
        for (int kk = 0; kk < 4; kk++) {
            const int k0 = kk * 8;
            uint32_t af[2][4];
#pragma unroll
            for (int mi = 0; mi < 2; mi++) {
                int r = mi * 16 + g;
                af[mi][0] = as[(r    ) * KW + k0 + tig];
                af[mi][1] = as[(r + 8) * KW + k0 + tig];
                af[mi][2] = as[(r    ) * KW + k0 + 4 + tig];
                af[mi][3] = as[(r + 8) * KW + k0 + 4 + tig];
            }
#pragma unroll
            for (int ni = 0; ni < 8; ni++) {
                uint32_t bf[2];
                int nr = ni * 8 + g;
                bf[0] = bs[nr * KW + k0 + tig];
                bf[1] = bs[nr * KW + k0 + 4 + tig];
                mma_f16(acc[0][ni], af[0], bf);
                mma_f16(acc[1][ni], af[1], bf);
            }
        }
    }

#pragma unroll
    for (int mi = 0; mi < 2; mi++) {
        int r0 = bm + wm * 32 + mi * 16 + g;
#pragma unroll
        for (int ni = 0; ni < 8; ni++) {
            int col = bn + wn * 64 + ni * 8 + 2 * tig;
            float b0 = 0.f, b1 = 0.f;
            if (bias) { b0 = bias[col]; b1 = bias[col + 1]; }
            float c0 = acc[mi][ni][0] + b0, c1 = acc[mi][ni][1] + b1;
            float c2 = acc[mi][ni][2] + b0, c3 = acc[mi][ni][3] + b1;
            if (OUTHALF) {
                __half* Ch = (__half*)Cptr;
                *(uint32_t*)&Ch[(size_t)r0 * EMB + col]       = pack_h2(c0, c1);
                *(uint32_t*)&Ch[(size_t)(r0 + 8) * EMB + col] = pack_h2(c2, c3);
            } else {
                float* Cf = (float*)Cptr;
                *(float2*)&Cf[(size_t)r0 * EMB + col]       = make_float2(c0, c1);
                *(float2*)&Cf[(size_t)(r0 + 8) * EMB + col] = make_float2(c2, c3);
            }
        }
    }
}

__global__ __launch_bounds__(256) void gemm_qkv(
    const __half* __restrict__ X,
    const __half* __restrict__ Wq, const __half* __restrict__ Wk,
    const __half* __restrict__ Wv,
    __half* __restrict__ Qo, __half* __restrict__ Ko, __half* __restrict__ Vo)
{
    extern __shared__ uint32_t sm[];
    const int wb = blockIdx.x >> 3;
    const int bn = (blockIdx.x & 7) * 128;
    const int bm = blockIdx.y * 128;
    const __half* B = (wb == 0) ? Wq : (wb == 1) ? Wk : Wv;
    __half*       C = (wb == 0) ? Qo : (wb == 1) ? Ko : Vo;
    gemm_h_body<true>(X, B, nullptr, C, bm, bn, sm);
}

__global__ __launch_bounds__(256) void gemm_out(
    const __half* __restrict__ A, const __half* __restrict__ W,
    const float* __restrict__ bias, float* __restrict__ C)
{
    extern __shared__ uint32_t sm[];
    gemm_h_body<false>(A, W, bias, C, blockIdx.y * 128, blockIdx.x * 128, sm);
}

// ---------------------------------------------------------------------------
// Flash attention (causal), fp16 mma + poly exp2. cp.async 2-stage K/V,
// ldmatrix for K/V fragments, REGISTER-resident P (C-frag == A-frag layout).
// Row stride AW=36 words. Smem: K stages, V stages, Q staging.
// ---------------------------------------------------------------------------
#define AW 36
#define KV_STAGE_B (64 * AW * 4)
#define PS_OFF_B   (4 * KV_STAGE_B)
#define ATTN_SMEM  (PS_OFF_B + 128 * AW * 4)   // 55296

__global__ __launch_bounds__(256, 2) void attn_mma(
    const __half* __restrict__ Q, const __half* __restrict__ K,
    const __half* __restrict__ V, __half* __restrict__ O)
{
    extern __shared__ __align__(16) uint32_t smw[];
    uint32_t* PsW = smw + PS_OFF_B / 4;
    const uint32_t smb = (uint32_t)__cvta_generic_to_shared(smw);

    const int tid  = threadIdx.x;
    const int lane = tid & 31, w = tid >> 5;
    const int g    = lane >> 2, tig = lane & 3;
    const int qt   = 15 - blockIdx.x;
    const int bh   = blockIdx.y;
    const int b    = bh >> 4, h = bh & 15;
    const size_t base  = (size_t)b * TS * EMB + (size_t)h * HD;
    const int    qbase = qt * 128;
    const int    nkt   = 2 * qt + 2;

    const int lm_t = lane & 7, lm_sel = lane >> 3;

    // ---- Prologue: issue cp.async for tile 0 -> stage 0.
    {
#pragma unroll
        for (int it = 0; it < 2; it++) {
            int v = tid + it * 256;
            int row = v >> 3, c = v & 7;
            cp16(smb + (row * AW + c * 4) * 4,
                 &K[base + (size_t)(row) * EMB + c * 8]);
        }
#pragma unroll
        for (int it = 0; it < 2; it++) {
            int v = tid + it * 256;
            int row = v >> 3, c = v & 7;
            cp16(smb + 2 * KV_STAGE_B + (row * AW + c * 4) * 4,
                 &V[base + (size_t)(row) * EMB + c * 8]);
        }
        CP_COMMIT();
    }

    // ---- Stage Q tile into Ps, lift to fragments.
#pragma unroll
    for (int it = 0; it < 4; it++) {
        int v = tid + it * 256;
        int row = v >> 3, c = v & 7;
        uint4 t = *(const uint4*)&Q[base + (size_t)(qbase + row) * EMB + c * 8];
        *(uint4*)&PsW[row * AW + c * 4] = t;
    }
    __syncthreads();

    uint32_t qa[4][4];
    {
        const int r0 = w * 16 + g;
#pragma unroll
        for (int kc = 0; kc < 4; kc++) {
            qa[kc][0] = PsW[(r0    ) * AW + kc * 8 + tig];
            qa[kc][1] = PsW[(r0 + 8) * AW + kc * 8 + tig];
            qa[kc][2] = PsW[(r0    ) * AW + kc * 8 + 4 + tig];
            qa[kc][3] = PsW[(r0 + 8) * AW + kc * 8 + 4 + tig];
        }
    }

    float m0 = -1e30f, m1 = -1e30f, l0 = 0.f, l1 = 0.f;
    float o[8][4];
#pragma unroll
    for (int ni = 0; ni < 8; ni++)
#pragma unroll
        for (int j = 0; j < 4; j++) o[ni][j] = 0.f;

    const float scale2 = 0.125f * 1.44269504089f;
    const int qrow_max = qbase + w * 16 + 15;

    for (int kt = 0; kt < nkt; kt++) {
        CP_WAIT0();
        __syncthreads();

        if (kt + 1 < nkt) {
            const int ns = (kt + 1) & 1;
#pragma unroll
            for (int it = 0; it < 2; it++) {
                int v = tid + it * 256;
                int row = v >> 3, c = v & 7;
                cp16(smb + ns * KV_STAGE_B + (row * AW + c * 4) * 4,
                     &K[base + (size_t)((kt + 1) * 64 + row) * EMB + c * 8]);
            }
#pragma unroll
            for (int it = 0; it < 2; it++) {
                int v = tid + it * 256;
                int row = v >> 3, c = v & 7;
                cp16(smb + 2 * KV_STAGE_B + ns * KV_STAGE_B + (row * AW + c * 4) * 4,
                     &V[base + (size_t)((kt + 1) * 64 + row) * EMB + c * 8]);
            }
            CP_COMMIT();
        }

        if (kt * 64 > qrow_max) continue;

        const uint32_t KsS = smb + (kt & 1) * KV_STAGE_B;
        const uint32_t VsS = smb + 2 * KV_STAGE_B + (kt & 1) * KV_STAGE_B;

        // ---- Scores: B-frags via ldmatrix.x4 from K rows.
        float sc[8][4];
#pragma unroll
        for (int ni = 0; ni < 8; ni++)
            sc[ni][0] = sc[ni][1] = sc[ni][2] = sc[ni][3] = 0.f;
#pragma unroll
        for (int np = 0; np < 4; np++) {
#pragma unroll
            for (int kc = 0; kc < 4; kc++) {
                int row  = np * 16 + ((lm_sel >> 1) << 3) + lm_t;
                int hoff = kc * 16 + ((lm_sel & 1) << 3);
                uint32_t b0, b1, b2, b3;
                ldm_x4(b0, b1, b2, b3, KsS + row * (AW * 4) + hoff * 2);
                uint32_t bfA[2] = {b0, b1}, bfB[2] = {b2, b3};
                mma_f16(sc[2 * np],     qa[kc], bfA);
                mma_f16(sc[2 * np + 1], qa[kc], bfB);
            }
        }

        // ---- Scale + causal mask
        const bool diag = (kt * 64 + 63 > qbase + w * 16);
        const int qg0 = qbase + w * 16 + g, qg1 = qg0 + 8;
#pragma unroll
        for (int ni = 0; ni < 8; ni++) {
#pragma unroll
            for (int j = 0; j < 4; j++) sc[ni][j] *= scale2;
            if (diag) {
                int kg = kt * 64 + ni * 8 + 2 * tig;
                if (kg     > qg0) sc[ni][0] = -1e30f;
                if (kg + 1 > qg0) sc[ni][1] = -1e30f;
                if (kg     > qg1) sc[ni][2] = -1e30f;
                if (kg + 1 > qg1) sc[ni][3] = -1e30f;
            }
        }

        // ---- Online softmax (base-2); P packed straight into A-fragments.
        float rm0 = -1e30f, rm1 = -1e30f;
#pragma unroll
        for (int ni = 0; ni < 8; ni++) {
            rm0 = fmaxf(rm0, fmaxf(sc[ni][0], sc[ni][1]));
            rm1 = fmaxf(rm1, fmaxf(sc[ni][2], sc[ni][3]));
        }
        rm0 = qmax(rm0); rm1 = qmax(rm1);
        float mn0 = fmaxf(m0, rm0), mn1 = fmaxf(m1, rm1);
        float a0 = exp2p(m0 - mn0), a1 = exp2p(m1 - mn1);
        m0 = mn0; m1 = mn1;
#pragma unroll
        for (int ni = 0; ni < 8; ni++) {
            o[ni][0] *= a0; o[ni][1] *= a0;
            o[ni][2] *= a1; o[ni][3] *= a1;
        }
        float s0 = 0.f, s1 = 0.f;
        uint32_t pp[8][2];   // pp[ni] = {pack(p0,p1) [row g], pack(p2,p3) [row g+8]}
#pragma unroll
        for (int ni = 0; ni < 8; ni++) {
            float p0 = exp2p(sc[ni][0] - mn0);
            float p1 = exp2p(sc[ni][1] - mn0);
            float p2 = exp2p(sc[ni][2] - mn1);
            float p3 = exp2p(sc[ni][3] - mn1);
            s0 += p0 + p1; s1 += p2 + p3;
            pp[ni][0] = pack_h2(p0, p1);
            pp[ni][1] = pack_h2(p2, p3);
        }
        l0 = l0 * a0 + qsum(s0);
        l1 = l1 * a1 + qsum(s1);

        // ---- PV: A = register P fragments; B via ldmatrix.x4.trans of V.
#pragma unroll
        for (int kc = 0; kc < 4; kc++) {
            uint32_t pa[4] = {pp[2*kc][0], pp[2*kc][1], pp[2*kc+1][0], pp[2*kc+1][1]};
#pragma unroll
            for (int ndp = 0; ndp < 4; ndp++) {
                int row  = kc * 16 + ((lm_sel & 1) << 3) + lm_t;
                int hoff = ndp * 16 + ((lm_sel >> 1) << 3);
                uint32_t b0, b1, b2, b3;
                ldm_x4_t(b0, b1, b2, b3, VsS + row * (AW * 4) + hoff * 2);
                uint32_t bfA[2] = {b0, b1}, bfB[2] = {b2, b3};
                mma_f16(o[2 * ndp],     pa, bfA);
                mma_f16(o[2 * ndp + 1], pa, bfB);
            }
        }
    }

    // ---- Normalize + store (half)
    const float inv0 = 1.f / l0, inv1 = 1.f / l1;
    const int q0 = qbase + w * 16 + g;
#pragma unroll
    for (int nd = 0; nd < 8; nd++) {
        int col = nd * 8 + 2 * tig;
        *(uint32_t*)&O[base + (size_t)q0 * EMB + col] =
            pack_h2(o[nd][0] * inv0, o[nd][1] * inv0);
        *(uint32_t*)&O[base + (size_t)(q0 + 8) * EMB + col] =
            pack_h2(o[nd][2] * inv1, o[nd][3] * inv1);
    }
}

// ---------------------------------------------------------------------------
extern "C" void kernel_launch(void* const* d_in, const int* in_sizes, int n_in,
                              void* d_out, int out_size)
{
    const float* x  = (const float*)d_in[0];
    // d_in[1] = mask (exact causal tril) -- applied analytically
    const float* Wq = (const float*)d_in[2];
    const float* Wk = (const float*)d_in[3];
    const float* Wv = (const float*)d_in[4];
    const float* Wo = (const float*)d_in[5];
    const float* bo = (const float*)d_in[6];
    float* out = (float*)d_out;

    __half *Qh, *Kh, *Vh, *Ah, *Xh, *Wqh, *Wkh, *Wvh, *Woh;
    cudaGetSymbolAddress((void**)&Qh, g_Qh);
    cudaGetSymbolAddress((void**)&Kh, g_Kh);
    cudaGetSymbolAddress((void**)&Vh, g_Vh);
    cudaGetSymbolAddress((void**)&Ah, g_Ah);
    cudaGetSymbolAddress((void**)&Xh, g_Xh);
    cudaGetSymbolAddress((void**)&Wqh, g_Wqh);
    cudaGetSymbolAddress((void**)&Wkh, g_Wkh);
    cudaGetSymbolAddress((void**)&Wvh, g_Wvh);
    cudaGetSymbolAddress((void**)&Woh, g_Woh);

    cudaFuncSetAttribute(gemm_qkv, cudaFuncAttributeMaxDynamicSharedMemorySize, GEMM_SMEM);
    cudaFuncSetAttribute(gemm_out, cudaFuncAttributeMaxDynamicSharedMemorySize, GEMM_SMEM);
    cudaFuncSetAttribute(attn_mma, cudaFuncAttributeMaxDynamicSharedMemorySize, ATTN_SMEM);

    const size_t total = (size_t)ROWS * EMB + 4 * (size_t)EMB * EMB;
    cvt_all<<<(int)(total / (256 * 8)), 256>>>(x, Wq, Wk, Wv, Wo,
                                               Xh, Wqh, Wkh, Wvh, Woh);

    dim3 qkvgrid(24, ROWS / 128);       // (24, 32)
    gemm_qkv<<<qkvgrid, 256, GEMM_SMEM>>>(Xh, Wqh, Wkh, Wvh, Qh, Kh, Vh);

    dim3 agrid(16, 2 * NHEADS);         // (16, 32)
    attn_mma<<<agrid, 256, ATTN_SMEM>>>(Qh, Kh, Vh, Ah);

    dim3 ogrid(EMB / 128, ROWS / 128);  // (8, 32)
    gemm_out<<<ogrid, 256, GEMM_SMEM>>>(Ah, Woh, bo, out);
}

// round 17
// speedup vs baseline: 1.7521x; 1.1239x over previous
#include <cuda_runtime.h>
#include <cuda_bf16.h>
#include <cuda_fp16.h>
#include <cstdint>

// Problem: MaskedSelfAttention  B=2, S=2048, E=1024, H=16, D=64, causal.
// R17: softmax exp2 -> single MUFU ex2.approx.f32 (poly was ~9 FMA-pipe ops;
//      MUFU is a separate, idle pipe and 67M exps need only ~15us chip-wide).
//      Everything else identical to R16 (GEMMs = R12 scalar-LDS, register-P attn).

#define TS   2048
#define EMB  1024
#define NHEADS 16
#define HD   64
#define ROWS (2*TS)

__device__ __half g_Qh[ROWS*EMB];
__device__ __half g_Kh[ROWS*EMB];
__device__ __half g_Vh[ROWS*EMB];
__device__ __half g_Ah[ROWS*EMB];
__device__ __half g_Xh[ROWS*EMB];
__device__ __half g_Wqh[EMB*EMB];
__device__ __half g_Wkh[EMB*EMB];
__device__ __half g_Wvh[EMB*EMB];
__device__ __half g_Woh[EMB*EMB];

__device__ __forceinline__ void mma_f16(float* d, const uint32_t* a, const uint32_t* b) {
    asm volatile(
        "mma.sync.aligned.m16n8k16.row.col.f32.f16.f16.f32 "
        "{%0,%1,%2,%3}, {%4,%5,%6,%7}, {%8,%9}, {%0,%1,%2,%3};"
        : "+f"(d[0]), "+f"(d[1]), "+f"(d[2]), "+f"(d[3])
        : "r"(a[0]), "r"(a[1]), "r"(a[2]), "r"(a[3]), "r"(b[0]), "r"(b[1]));
}

__device__ __forceinline__ uint32_t pack_h2(float x, float y) {
    __half2 h = __floats2half2_rn(x, y);
    return *(uint32_t*)&h;
}

__device__ __forceinline__ void ldm_x4(uint32_t& r0, uint32_t& r1,
                                       uint32_t& r2, uint32_t& r3, uint32_t addr) {
    asm volatile("ldmatrix.sync.aligned.m8n8.x4.shared.b16 {%0,%1,%2,%3}, [%4];"
        : "=r"(r0), "=r"(r1), "=r"(r2), "=r"(r3) : "r"(addr));
}
__device__ __forceinline__ void ldm_x4_t(uint32_t& r0, uint32_t& r1,
                                         uint32_t& r2, uint32_t& r3, uint32_t addr) {
    asm volatile("ldmatrix.sync.aligned.m8n8.x4.trans.shared.b16 {%0,%1,%2,%3}, [%4];"
        : "=r"(r0), "=r"(r1), "=r"(r2), "=r"(r3) : "r"(addr));
}

__device__ __forceinline__ void cp16(uint32_t saddr, const void* g) {
    asm volatile("cp.async.cg.shared.global [%0], [%1], 16;" :: "r"(saddr), "l"(g));
}
#define CP_COMMIT() asm volatile("cp.async.commit_group;" ::: "memory")
#define CP_WAIT0()  asm volatile("cp.async.wait_group 0;" ::: "memory")

// exp2 via MUFU (separate pipe; ~2 ulp; inputs are <= 0).
__device__ __forceinline__ float exp2p(float d) {
    float r;
    asm("ex2.approx.f32 %0, %1;" : "=f"(r) : "f"(d));
    return r;
}

__device__ __forceinline__ float qmax(float v) {
    v = fmaxf(v, __shfl_xor_sync(0xffffffffu, v, 1));
    v = fmaxf(v, __shfl_xor_sync(0xffffffffu, v, 2));
    return v;
}
__device__ __forceinline__ float qsum(float v) {
    v += __shfl_xor_sync(0xffffffffu, v, 1);
    v += __shfl_xor_sync(0xffffffffu, v, 2);
    return v;
}

// ---------------------------------------------------------------------------
// Prepass: convert x (4M) + 4 weights (1M each) fp32 -> fp16. 8 elems/thread.
// ---------------------------------------------------------------------------
__global__ __launch_bounds__(256) void cvt_all(
    const float* __restrict__ X,
    const float* __restrict__ Wq, const float* __restrict__ Wk,
    const float* __restrict__ Wv, const float* __restrict__ Wo,
    __half* __restrict__ Xh, __half* __restrict__ Wqh, __half* __restrict__ Wkh,
    __half* __restrict__ Wvh, __half* __restrict__ Woh)
{
    size_t i = ((size_t)blockIdx.x * 256 + threadIdx.x) * 8;
    const float* src; __half* dst; size_t off;
    const size_t NX = (size_t)ROWS * EMB, NW = (size_t)EMB * EMB;
    if (i < NX)               { src = X;  dst = Xh;  off = i; }
    else if (i < NX + NW)     { src = Wq; dst = Wqh; off = i - NX; }
    else if (i < NX + 2*NW)   { src = Wk; dst = Wkh; off = i - NX - NW; }
    else if (i < NX + 3*NW)   { src = Wv; dst = Wvh; off = i - NX - 2*NW; }
    else                      { src = Wo; dst = Woh; off = i - NX - 3*NW; }
    float4 a = *(const float4*)&src[off];
    float4 b = *(const float4*)&src[off + 4];
    uint4 u = make_uint4(pack_h2(a.x, a.y), pack_h2(a.z, a.w),
                         pack_h2(b.x, b.y), pack_h2(b.z, b.w));
    *(uint4*)&dst[off] = u;
}

// ---------------------------------------------------------------------------
// fp16 GEMM (R12 proven): CTA 128x128, BK=64, 8 warps, cp.async 2-stage,
// scalar-LDS fragment loads. KW=36 conflict-free.
// ---------------------------------------------------------------------------
#define KW 36
#define TILE_W (128 * KW)
#define BUF_W  (2 * TILE_W)
#define GEMM_SMEM (2 * BUF_W * 4)   // 73728 B

template <bool OUTHALF>
__device__ __forceinline__ void gemm_h_body(
    const __half* __restrict__ A, const __half* __restrict__ B,
    const float* __restrict__ bias, void* __restrict__ Cptr,
    int bm, int bn, uint32_t* sm)
{
    const uint32_t smb = (uint32_t)__cvta_generic_to_shared(sm);
    const int tid  = threadIdx.x;
    const int lane = tid & 31, warp = tid >> 5;
    const int g    = lane >> 2, tig = lane & 3;
    const int wm   = warp >> 1, wn = warp & 1;

    int lrow[4], lc[4];
#pragma unroll
    for (int it = 0; it < 4; it++) {
        int v = tid + it * 256;
        lrow[it] = v >> 3;
        lc[it]   = (v & 7) * 8;
    }

    float acc[2][8][4];
#pragma unroll
    for (int mi = 0; mi < 2; mi++)
#pragma unroll
        for (int ni = 0; ni < 8; ni++)
#pragma unroll
            for (int j = 0; j < 4; j++) acc[mi][ni][j] = 0.f;

#pragma unroll
    for (int it = 0; it < 4; it++) {
        uint32_t so = (lrow[it] * KW + lc[it] / 2) * 4;
        cp16(smb + so,              &A[(size_t)(bm + lrow[it]) * EMB + lc[it]]);
        cp16(smb + TILE_W * 4 + so, &B[(size_t)(bn + lrow[it]) * EMB + lc[it]]);
    }
    CP_COMMIT();

    for (int ks = 0; ks < 16; ks++) {
        const int cur = ks & 1;
        CP_WAIT0();
        __syncthreads();

        if (ks + 1 < 16) {
            const uint32_t sb2 = smb + (cur ^ 1) * BUF_W * 4;
#pragma unroll
            for (int it = 0; it < 4; it++) {
                uint32_t so = (lrow[it] * KW + lc[it] / 2) * 4;
                cp16(sb2 + so,              &A[(size_t)(bm + lrow[it]) * EMB + (ks + 1) * 64 + lc[it]]);
                cp16(sb2 + TILE_W * 4 + so, &B[(size_t)(bn + lrow[it]) * EMB + (ks + 1) * 64 + lc[it]]);
            }
            CP_COMMIT();
        }

        const uint32_t* as = sm + cur * BUF_W + (wm * 32) * KW;
        const uint32_t* bs = sm + cur * BUF_W + TILE_W + (wn * 64) * KW;

#pragma unroll
        for (int kk = 0; kk < 4; kk++) {
            const int k0 = kk * 8;
            uint32_t af[2][4];
#pragma unroll
            for (int mi = 0; mi < 2; mi++) {
                int r = mi * 16 + g;
                af[mi][0] = as[(r    ) * KW + k0 + tig];
                af[mi][1] = as[(r + 8) * KW + k0 + tig];
                af[mi][2] = as[(r    ) * KW + k0 + 4 + tig];
                af[mi][3] = as[(r + 8) * KW + k0 + 4 + tig];
            }
#pragma unroll
            for (int ni = 0; ni < 8; ni++) {
                uint32_t bf[2];
                int nr = ni * 8 + g;
                bf[0] = bs[nr * KW + k0 + tig];
                bf[1] = bs[nr * KW + k0 + 4 + tig];
                mma_f16(acc[0][ni], af[0], bf);
                mma_f16(acc[1][ni], af[1], bf);
            }
        }
    }

#pragma unroll
    for (int mi = 0; mi < 2; mi++) {
        int r0 = bm + wm * 32 + mi * 16 + g;
#pragma unroll
        for (int ni = 0; ni < 8; ni++) {
            int col = bn + wn * 64 + ni * 8 + 2 * tig;
            float b0 = 0.f, b1 = 0.f;
            if (bias) { b0 = bias[col]; b1 = bias[col + 1]; }
            float c0 = acc[mi][ni][0] + b0, c1 = acc[mi][ni][1] + b1;
            float c2 = acc[mi][ni][2] + b0, c3 = acc[mi][ni][3] + b1;
            if (OUTHALF) {
                __half* Ch = (__half*)Cptr;
                *(uint32_t*)&Ch[(size_t)r0 * EMB + col]       = pack_h2(c0, c1);
                *(uint32_t*)&Ch[(size_t)(r0 + 8) * EMB + col] = pack_h2(c2, c3);
            } else {
                float* Cf = (float*)Cptr;
                *(float2*)&Cf[(size_t)r0 * EMB + col]       = make_float2(c0, c1);
                *(float2*)&Cf[(size_t)(r0 + 8) * EMB + col] = make_float2(c2, c3);
            }
        }
    }
}

__global__ __launch_bounds__(256) void gemm_qkv(
    const __half* __restrict__ X,
    const __half* __restrict__ Wq, const __half* __restrict__ Wk,
    const __half* __restrict__ Wv,
    __half* __restrict__ Qo, __half* __restrict__ Ko, __half* __restrict__ Vo)
{
    extern __shared__ uint32_t sm[];
    const int wb = blockIdx.x >> 3;
    const int bn = (blockIdx.x & 7) * 128;
    const int bm = blockIdx.y * 128;
    const __half* B = (wb == 0) ? Wq : (wb == 1) ? Wk : Wv;
    __half*       C = (wb == 0) ? Qo : (wb == 1) ? Ko : Vo;
    gemm_h_body<true>(X, B, nullptr, C, bm, bn, sm);
}

__global__ __launch_bounds__(256) void gemm_out(
    const __half* __restrict__ A, const __half* __restrict__ W,
    const float* __restrict__ bias, float* __restrict__ C)
{
    extern __shared__ uint32_t sm[];
    gemm_h_body<false>(A, W, bias, C, blockIdx.y * 128, blockIdx.x * 128, sm);
}

// ---------------------------------------------------------------------------
// Flash attention (causal), fp16 mma + MUFU exp2. cp.async 2-stage K/V,
// ldmatrix K/V fragments, register-resident P. Row stride AW=36 words.
// ---------------------------------------------------------------------------
#define AW 36
#define KV_STAGE_B (64 * AW * 4)
#define PS_OFF_B   (4 * KV_STAGE_B)
#define ATTN_SMEM  (PS_OFF_B + 128 * AW * 4)   // 55296

__global__ __launch_bounds__(256, 2) void attn_mma(
    const __half* __restrict__ Q, const __half* __restrict__ K,
    const __half* __restrict__ V, __half* __restrict__ O)
{
    extern __shared__ __align__(16) uint32_t smw[];
    uint32_t* PsW = smw + PS_OFF_B / 4;
    const uint32_t smb = (uint32_t)__cvta_generic_to_shared(smw);

    const int tid  = threadIdx.x;
    const int lane = tid & 31, w = tid >> 5;
    const int g    = lane >> 2, tig = lane & 3;
    const int qt   = 15 - blockIdx.x;
    const int bh   = blockIdx.y;
    const int b    = bh >> 4, h = bh & 15;
    const size_t base  = (size_t)b * TS * EMB + (size_t)h * HD;
    const int    qbase = qt * 128;
    const int    nkt   = 2 * qt + 2;

    const int lm_t = lane & 7, lm_sel = lane >> 3;

    // ---- Prologue: issue cp.async for tile 0 -> stage 0.
    {
#pragma unroll
        for (int it = 0; it < 2; it++) {
            int v = tid + it * 256;
            int row = v >> 3, c = v & 7;
            cp16(smb + (row * AW + c * 4) * 4,
                 &K[base + (size_t)(row) * EMB + c * 8]);
        }
#pragma unroll
        for (int it = 0; it < 2; it++) {
            int v = tid + it * 256;
            int row = v >> 3, c = v & 7;
            cp16(smb + 2 * KV_STAGE_B + (row * AW + c * 4) * 4,
                 &V[base + (size_t)(row) * EMB + c * 8]);
        }
        CP_COMMIT();
    }

    // ---- Stage Q tile into Ps, lift to fragments.
#pragma unroll
    for (int it = 0; it < 4; it++) {
        int v = tid + it * 256;
        int row = v >> 3, c = v & 7;
        uint4 t = *(const uint4*)&Q[base + (size_t)(qbase + row) * EMB + c * 8];
        *(uint4*)&PsW[row * AW + c * 4] = t;
    }
    __syncthreads();

    uint32_t qa[4][4];
    {
        const int r0 = w * 16 + g;
#pragma unroll
        for (int kc = 0; kc < 4; kc++) {
            qa[kc][0] = PsW[(r0    ) * AW + kc * 8 + tig];
            qa[kc][1] = PsW[(r0 + 8) * AW + kc * 8 + tig];
            qa[kc][2] = PsW[(r0    ) * AW + kc * 8 + 4 + tig];
            qa[kc][3] = PsW[(r0 + 8) * AW + kc * 8 + 4 + tig];
        }
    }

    float m0 = -1e30f, m1 = -1e30f, l0 = 0.f, l1 = 0.f;
    float o[8][4];
#pragma unroll
    for (int ni = 0; ni < 8; ni++)
#pragma unroll
        for (int j = 0; j < 4; j++) o[ni][j] = 0.f;

    const float scale2 = 0.125f * 1.44269504089f;
    const int qrow_max = qbase + w * 16 + 15;

    for (int kt = 0; kt < nkt; kt++) {
        CP_WAIT0();
        __syncthreads();

        if (kt + 1 < nkt) {
            const int ns = (kt + 1) & 1;
#pragma unroll
            for (int it = 0; it < 2; it++) {
                int v = tid + it * 256;
                int row = v >> 3, c = v & 7;
                cp16(smb + ns * KV_STAGE_B + (row * AW + c * 4) * 4,
                     &K[base + (size_t)((kt + 1) * 64 + row) * EMB + c * 8]);
            }
#pragma unroll
            for (int it = 0; it < 2; it++) {
                int v = tid + it * 256;
                int row = v >> 3, c = v & 7;
                cp16(smb + 2 * KV_STAGE_B + ns * KV_STAGE_B + (row * AW + c * 4) * 4,
                     &V[base + (size_t)((kt + 1) * 64 + row) * EMB + c * 8]);
            }
            CP_COMMIT();
        }

        if (kt * 64 > qrow_max) continue;

        const uint32_t KsS = smb + (kt & 1) * KV_STAGE_B;
        const uint32_t VsS = smb + 2 * KV_STAGE_B + (kt & 1) * KV_STAGE_B;

        // ---- Scores: B-frags via ldmatrix.x4 from K rows.
        float sc[8][4];
#pragma unroll
        for (int ni = 0; ni < 8; ni++)
            sc[ni][0] = sc[ni][1] = sc[ni][2] = sc[ni][3] = 0.f;
#pragma unroll
        for (int np = 0; np < 4; np++) {
#pragma unroll
            for (int kc = 0; kc < 4; kc++) {
                int row  = np * 16 + ((lm_sel >> 1) << 3) + lm_t;
                int hoff = kc * 16 + ((lm_sel & 1) << 3);
                uint32_t b0, b1, b2, b3;
                ldm_x4(b0, b1, b2, b3, KsS + row * (AW * 4) + hoff * 2);
                uint32_t bfA[2] = {b0, b1}, bfB[2] = {b2, b3};
                mma_f16(sc[2 * np],     qa[kc], bfA);
                mma_f16(sc[2 * np + 1], qa[kc], bfB);
            }
        }

        // ---- Scale + causal mask
        const bool diag = (kt * 64 + 63 > qbase + w * 16);
        const int qg0 = qbase + w * 16 + g, qg1 = qg0 + 8;
#pragma unroll
        for (int ni = 0; ni < 8; ni++) {
#pragma unroll
            for (int j = 0; j < 4; j++) sc[ni][j] *= scale2;
            if (diag) {
                int kg = kt * 64 + ni * 8 + 2 * tig;
                if (kg     > qg0) sc[ni][0] = -1e30f;
                if (kg + 1 > qg0) sc[ni][1] = -1e30f;
                if (kg     > qg1) sc[ni][2] = -1e30f;
                if (kg + 1 > qg1) sc[ni][3] = -1e30f;
            }
        }

        // ---- Online softmax (base-2, MUFU); P packed straight into A-frags.
        float rm0 = -1e30f, rm1 = -1e30f;
#pragma unroll
        for (int ni = 0; ni < 8; ni++) {
            rm0 = fmaxf(rm0, fmaxf(sc[ni][0], sc[ni][1]));
            rm1 = fmaxf(rm1, fmaxf(sc[ni][2], sc[ni][3]));
        }
        rm0 = qmax(rm0); rm1 = qmax(rm1);
        float mn0 = fmaxf(m0, rm0), mn1 = fmaxf(m1, rm1);
        float a0 = exp2p(m0 - mn0), a1 = exp2p(m1 - mn1);
        m0 = mn0; m1 = mn1;
#pragma unroll
        for (int ni = 0; ni < 8; ni++) {
            o[ni][0] *= a0; o[ni][1] *= a0;
            o[ni][2] *= a1; o[ni][3] *= a1;
        }
        float s0 = 0.f, s1 = 0.f;
        uint32_t pp[8][2];
#pragma unroll
        for (int ni = 0; ni < 8; ni++) {
            float p0 = exp2p(sc[ni][0] - mn0);
            float p1 = exp2p(sc[ni][1] - mn0);
            float p2 = exp2p(sc[ni][2] - mn1);
            float p3 = exp2p(sc[ni][3] - mn1);
            s0 += p0 + p1; s1 += p2 + p3;
            pp[ni][0] = pack_h2(p0, p1);
            pp[ni][1] = pack_h2(p2, p3);
        }
        l0 = l0 * a0 + qsum(s0);
        l1 = l1 * a1 + qsum(s1);

        // ---- PV: A = register P fragments; B via ldmatrix.x4.trans of V.
#pragma unroll
        for (int kc = 0; kc < 4; kc++) {
            uint32_t pa[4] = {pp[2*kc][0], pp[2*kc][1], pp[2*kc+1][0], pp[2*kc+1][1]};
#pragma unroll
            for (int ndp = 0; ndp < 4; ndp++) {
                int row  = kc * 16 + ((lm_sel & 1) << 3) + lm_t;
                int hoff = ndp * 16 + ((lm_sel >> 1) << 3);
                uint32_t b0, b1, b2, b3;
                ldm_x4_t(b0, b1, b2, b3, VsS + row * (AW * 4) + hoff * 2);
                uint32_t bfA[2] = {b0, b1}, bfB[2] = {b2, b3};
                mma_f16(o[2 * ndp],     pa, bfA);
                mma_f16(o[2 * ndp + 1], pa, bfB);
            }
        }
    }

    // ---- Normalize + store (half)
    const float inv0 = 1.f / l0, inv1 = 1.f / l1;
    const int q0 = qbase + w * 16 + g;
#pragma unroll
    for (int nd = 0; nd < 8; nd++) {
        int col = nd * 8 + 2 * tig;
        *(uint32_t*)&O[base + (size_t)q0 * EMB + col] =
            pack_h2(o[nd][0] * inv0, o[nd][1] * inv0);
        *(uint32_t*)&O[base + (size_t)(q0 + 8) * EMB + col] =
            pack_h2(o[nd][2] * inv1, o[nd][3] * inv1);
    }
}

// ---------------------------------------------------------------------------
extern "C" void kernel_launch(void* const* d_in, const int* in_sizes, int n_in,
                              void* d_out, int out_size)
{
    const float* x  = (const float*)d_in[0];
    // d_in[1] = mask (exact causal tril) -- applied analytically
    const float* Wq = (const float*)d_in[2];
    const float* Wk = (const float*)d_in[3];
    const float* Wv = (const float*)d_in[4];
    const float* Wo = (const float*)d_in[5];
    const float* bo = (const float*)d_in[6];
    float* out = (float*)d_out;

    __half *Qh, *Kh, *Vh, *Ah, *Xh, *Wqh, *Wkh, *Wvh, *Woh;
    cudaGetSymbolAddress((void**)&Qh, g_Qh);
    cudaGetSymbolAddress((void**)&Kh, g_Kh);
    cudaGetSymbolAddress((void**)&Vh, g_Vh);
    cudaGetSymbolAddress((void**)&Ah, g_Ah);
    cudaGetSymbolAddress((void**)&Xh, g_Xh);
    cudaGetSymbolAddress((void**)&Wqh, g_Wqh);
    cudaGetSymbolAddress((void**)&Wkh, g_Wkh);
    cudaGetSymbolAddress((void**)&Wvh, g_Wvh);
    cudaGetSymbolAddress((void**)&Woh, g_Woh);

    cudaFuncSetAttribute(gemm_qkv, cudaFuncAttributeMaxDynamicSharedMemorySize, GEMM_SMEM);
    cudaFuncSetAttribute(gemm_out, cudaFuncAttributeMaxDynamicSharedMemorySize, GEMM_SMEM);
    cudaFuncSetAttribute(attn_mma, cudaFuncAttributeMaxDynamicSharedMemorySize, ATTN_SMEM);

    const size_t total = (size_t)ROWS * EMB + 4 * (size_t)EMB * EMB;
    cvt_all<<<(int)(total / (256 * 8)), 256>>>(x, Wq, Wk, Wv, Wo,
                                               Xh, Wqh, Wkh, Wvh, Woh);

    dim3 qkvgrid(24, ROWS / 128);       // (24, 32)
    gemm_qkv<<<qkvgrid, 256, GEMM_SMEM>>>(Xh, Wqh, Wkh, Wvh, Qh, Kh, Vh);

    dim3 agrid(16, 2 * NHEADS);         // (16, 32)
    attn_mma<<<agrid, 256, ATTN_SMEM>>>(Qh, Kh, Vh, Ah);

    dim3 ogrid(EMB / 128, ROWS / 128);  // (8, 32)
    gemm_out<<<ogrid, 256, GEMM_SMEM>>>(Ah, Woh, bo, out);
}